// round 13
// baseline (speedup 1.0000x reference)
#include <cuda_runtime.h>
#include <math.h>

#define TT 8
#define NI 20000
#define NK 50000
#define FF 128
#define HH 256
#define OO 128
#define EE 500000
#define MAXS 512
#define NKW ((NK + 31) / 32)        // 1563 bitmap words
#define SCAN_BLK 123                 // ceil((EE/4) / (4*256))
#define SCAN_STRIDE (SCAN_BLK * 256)
#define FULLW 0xffffffffu

// ---------------- scratch (device globals; no allocation allowed) ----------------
__device__ int      g_item_flag[TT][NK];   // -1 empty, -2 marked, >=0 slot
__device__ int      g_item_mult[TT][NK];   // edge multiplicity (src,target) in e2
__device__ unsigned g_bitmap[TT][NKW];     // 1 bit per slotted item
__device__ int      g_item_id[TT][MAXS];
__device__ int      g_item_cnt[TT][MAXS];  // e1 in-degree of needed item
__device__ float    g_item_acc[TT][MAXS][FF];
__device__ float    g_hitem[TT][MAXS][HH];
__device__ int      g_num_items[TT];
__device__ float    g_accx[TT][FF];        // sum of x_item over target's e2 edges
__device__ int      g_edge_cnt[TT];
__device__ float    g_seq[TT][OO];
__device__ float    g_gi[TT][3 * HH];
__device__ float    g_hbuf[2][HH];
__device__ float    g_rnn[TT][HH];

// ---------------- init / reset (R11-proven) ----------------
__global__ void k_init() {
    int idx = blockIdx.x * blockDim.x + threadIdx.x;
    if (idx < TT * NK) {
        ((int*)g_item_flag)[idx] = -1;
        ((int*)g_item_mult)[idx] = 0;
    }
    if (idx < TT * MAXS * FF) ((float*)g_item_acc)[idx] = 0.0f;
    if (idx < TT * MAXS)      ((int*)g_item_cnt)[idx] = 0;
    if (idx < TT * FF)        ((float*)g_accx)[idx] = 0.0f;
    if (idx < TT * NKW)       ((unsigned*)g_bitmap)[idx] = 0u;
    if (idx < TT) { g_edge_cnt[idx] = 0; g_num_items[idx] = 0; }
    if (idx < 2 * HH) ((float*)g_hbuf)[idx] = 0.0f;
}

// ---------------- pass A: scan e2, warp-cooperative hit path (R11-proven) ----------------
__global__ void k_scan_e2(const int* __restrict__ e2s, const int* __restrict__ e2d,
                          const float* __restrict__ x_item, const int* __restrict__ tgtp) {
    int t = blockIdx.y;
    int tgt = *tgtp;
    const int4* d4 = (const int4*)(e2d + (size_t)t * EE);
    const int* s = e2s + (size_t)t * EE;
    int lane = threadIdx.x & 31;
    int tidx = blockIdx.x * blockDim.x + threadIdx.x;
    int4 v[4]; int ok[4];
    #pragma unroll
    for (int k = 0; k < 4; k++) {
        int idx = tidx + k * SCAN_STRIDE;
        ok[k] = idx < EE / 4;
        v[k] = ok[k] ? __ldg(d4 + idx) : make_int4(-1, -1, -1, -1);
    }
    #pragma unroll
    for (int k = 0; k < 4; k++) {
        int e = 4 * (tidx + k * SCAN_STRIDE);
        #pragma unroll
        for (int j = 0; j < 4; j++) {
            int dv = (j == 0) ? v[k].x : (j == 1) ? v[k].y : (j == 2) ? v[k].z : v[k].w;
            bool hit = ok[k] && (dv == tgt);
            unsigned m = __ballot_sync(FULLW, hit);
            while (m) {
                int ldr = __ffs(m) - 1;
                m &= m - 1;
                int eb = __shfl_sync(FULLW, e + j, ldr);
                int src = 0;
                if (lane == ldr) src = s[eb];
                src = __shfl_sync(FULLW, src, ldr);
                if (lane == 0) {
                    atomicAdd(&g_edge_cnt[t], 1);
                    atomicAdd(&g_item_mult[t][src], 1);
                    int old = atomicExch(&g_item_flag[t][src], -2);
                    if (old == -1) {
                        int sl = atomicAdd(&g_num_items[t], 1);
                        if (sl < MAXS) g_item_id[t][sl] = src;
                    }
                }
                float4 xv = ((const float4*)(x_item + ((size_t)t * NK + src) * FF))[lane];
                atomicAdd(&g_accx[t][4 * lane + 0], xv.x);
                atomicAdd(&g_accx[t][4 * lane + 1], xv.y);
                atomicAdd(&g_accx[t][4 * lane + 2], xv.z);
                atomicAdd(&g_accx[t][4 * lane + 3], xv.w);
            }
        }
    }
}

// ---------------- pass A2: assign slot ids + build bitmap (R11-proven) ----------------
__global__ void k_assign() {
    int t = blockIdx.x;
    if (threadIdx.x == 0 && g_num_items[t] > MAXS) g_num_items[t] = MAXS;
    __syncthreads();
    int n = g_num_items[t];
    for (int k = threadIdx.x; k < n; k += blockDim.x) {
        int id = g_item_id[t][k];
        g_item_flag[t][id] = k;
        atomicOr(&g_bitmap[t][id >> 5], 1u << (id & 31));
    }
}

// ---------------- pass B: scan e1, bitmap + warp-cooperative hit path (R11-proven) ----------------
__global__ void k_scan_e1(const int* __restrict__ e1s, const int* __restrict__ e1d,
                          const float* __restrict__ x_inf) {
    int t = blockIdx.y;
    __shared__ unsigned bm[NKW];
    for (int w = threadIdx.x; w < NKW; w += blockDim.x) bm[w] = g_bitmap[t][w];
    __syncthreads();
    const int4* d4 = (const int4*)(e1d + (size_t)t * EE);
    const int* s = e1s + (size_t)t * EE;
    const int* flag = g_item_flag[t];
    int lane = threadIdx.x & 31;
    int tidx = blockIdx.x * blockDim.x + threadIdx.x;
    int4 v[4]; int ok[4];
    #pragma unroll
    for (int k = 0; k < 4; k++) {
        int idx = tidx + k * SCAN_STRIDE;
        ok[k] = idx < EE / 4;
        v[k] = ok[k] ? __ldg(d4 + idx) : make_int4(0, 0, 0, 0);
    }
    #pragma unroll
    for (int k = 0; k < 4; k++) {
        int e = 4 * (tidx + k * SCAN_STRIDE);
        #pragma unroll
        for (int j = 0; j < 4; j++) {
            int dv = (j == 0) ? v[k].x : (j == 1) ? v[k].y : (j == 2) ? v[k].z : v[k].w;
            int sl = -1;
            if (ok[k] && ((bm[dv >> 5] >> (dv & 31)) & 1u)) sl = flag[dv];
            bool hit = sl >= 0;
            unsigned m = __ballot_sync(FULLW, hit);
            while (m) {
                int ldr = __ffs(m) - 1;
                m &= m - 1;
                int slb = __shfl_sync(FULLW, sl, ldr);
                int eb = __shfl_sync(FULLW, e + j, ldr);
                int src = 0;
                if (lane == ldr) src = s[eb];
                src = __shfl_sync(FULLW, src, ldr);
                if (lane == 0) atomicAdd(&g_item_cnt[t][slb], 1);
                float4 xv = ((const float4*)(x_inf + ((size_t)t * NI + src) * FF))[lane];
                atomicAdd(&g_item_acc[t][slb][4 * lane + 0], xv.x);
                atomicAdd(&g_item_acc[t][slb][4 * lane + 1], xv.y);
                atomicAdd(&g_item_acc[t][slb][4 * lane + 2], xv.z);
                atomicAdd(&g_item_acc[t][slb][4 * lane + 3], xv.w);
            }
        }
    }
}

__device__ __forceinline__ float warp_sum(float v) {
    #pragma unroll
    for (int off = 16; off > 0; off >>= 1) v += __shfl_down_sync(0xffffffffu, v, off);
    return v;
}

// 4 interleaved reduction chains — pipelined shfl latency
__device__ __forceinline__ void warp_sum4(float& a, float& b, float& c, float& d) {
    #pragma unroll
    for (int off = 16; off > 0; off >>= 1) {
        a += __shfl_down_sync(FULLW, a, off);
        b += __shfl_down_sync(FULLW, b, off);
        c += __shfl_down_sync(FULLW, c, off);
        d += __shfl_down_sync(FULLW, d, off);
    }
}

__device__ __forceinline__ float dot4(float4 w, float4 v) {
    return w.x * v.x + w.y * v.y + w.z * v.z + w.w * v.w;
}

// ---------------- pass C: h_item, 4-row ILP warp matvec ----------------
__global__ void k_hitem(const float* __restrict__ x_item,
                        const float* __restrict__ W1a_l, const float* __restrict__ b1a_l,
                        const float* __restrict__ W1a_r) {
    int t = blockIdx.y;
    int tid = threadIdx.x;
    int wid = tid >> 5, lane = tid & 31;
    __shared__ float4 mean4[FF / 4], xrow4[FF / 4];
    for (int sl = blockIdx.x; sl < g_num_items[t]; sl += gridDim.x) {
        int id = g_item_id[t][sl];
        float c = fmaxf((float)g_item_cnt[t][sl], 1.0f);
        if (tid < FF) {
            ((float*)mean4)[tid] = g_item_acc[t][sl][tid] / c;
            ((float*)xrow4)[tid] = x_item[((size_t)t * NK + id) * FF + tid];
        }
        __syncthreads();
        float4 m = mean4[lane], x = xrow4[lane];
        // each warp: 8 groups of 4 consecutive rows; 8 loads in flight, 4 chains pipelined
        for (int g = wid; g < HH / 4; g += 8) {
            int h = 4 * g;
            float4 wl0 = ((const float4*)(W1a_l + (size_t)(h + 0) * FF))[lane];
            float4 wl1 = ((const float4*)(W1a_l + (size_t)(h + 1) * FF))[lane];
            float4 wl2 = ((const float4*)(W1a_l + (size_t)(h + 2) * FF))[lane];
            float4 wl3 = ((const float4*)(W1a_l + (size_t)(h + 3) * FF))[lane];
            float4 wr0 = ((const float4*)(W1a_r + (size_t)(h + 0) * FF))[lane];
            float4 wr1 = ((const float4*)(W1a_r + (size_t)(h + 1) * FF))[lane];
            float4 wr2 = ((const float4*)(W1a_r + (size_t)(h + 2) * FF))[lane];
            float4 wr3 = ((const float4*)(W1a_r + (size_t)(h + 3) * FF))[lane];
            float a0 = dot4(wl0, m) + dot4(wr0, x);
            float a1 = dot4(wl1, m) + dot4(wr1, x);
            float a2 = dot4(wl2, m) + dot4(wr2, x);
            float a3 = dot4(wl3, m) + dot4(wr3, x);
            warp_sum4(a0, a1, a2, a3);
            if (lane == 0) {
                g_hitem[t][sl][h + 0] = fmaxf(a0 + b1a_l[h + 0], 0.0f);
                g_hitem[t][sl][h + 1] = fmaxf(a1 + b1a_l[h + 1], 0.0f);
                g_hitem[t][sl][h + 2] = fmaxf(a2 + b1a_l[h + 2], 0.0f);
                g_hitem[t][sl][h + 3] = fmaxf(a3 + b1a_l[h + 3], 0.0f);
            }
        }
        __syncthreads();
    }
}

// ---------------- pass D: h_inf[target] + o_inf[target], COALESCED (R8-proven) ----------------
__global__ void k_oinf(const float* __restrict__ x_inf,
                       const float* __restrict__ W1b_l, const float* __restrict__ b1b_l,
                       const float* __restrict__ W1b_r,
                       const float* __restrict__ W2b_l, const float* __restrict__ b2b_l,
                       const float* __restrict__ W2b_r,
                       const int* __restrict__ tgtp) {
    int t = blockIdx.x;
    int tid = threadIdx.x;
    int wid = tid >> 5, lane = tid & 31;
    int tgt = *tgtp;
    __shared__ float4 meanx4[FF / 4], xt4[FF / 4];
    __shared__ float4 hinf4[HH / 4], meanh4[HH / 4];
    __shared__ float multw[MAXS];
    float ec = fmaxf((float)g_edge_cnt[t], 1.0f);
    int n = g_num_items[t];
    if (n > MAXS) n = MAXS;
    if (tid < FF) {
        ((float*)meanx4)[tid] = g_accx[t][tid] / ec;
        ((float*)xt4)[tid]    = x_inf[((size_t)t * NI + tgt) * FF + tid];
    }
    for (int k = tid; k < n; k += blockDim.x)
        multw[k] = (float)g_item_mult[t][g_item_id[t][k]];
    __syncthreads();

    {
        float mh = 0.0f;
        for (int k = 0; k < n; k++) mh += multw[k] * g_hitem[t][k][tid];
        ((float*)meanh4)[tid] = mh / ec;
    }
    {
        float4 m = meanx4[lane], x = xt4[lane];
        for (int g = wid; g < HH / 4; g += 8) {
            int h = 4 * g;
            float4 wl0 = ((const float4*)(W1b_l + (size_t)(h + 0) * FF))[lane];
            float4 wl1 = ((const float4*)(W1b_l + (size_t)(h + 1) * FF))[lane];
            float4 wl2 = ((const float4*)(W1b_l + (size_t)(h + 2) * FF))[lane];
            float4 wl3 = ((const float4*)(W1b_l + (size_t)(h + 3) * FF))[lane];
            float4 wr0 = ((const float4*)(W1b_r + (size_t)(h + 0) * FF))[lane];
            float4 wr1 = ((const float4*)(W1b_r + (size_t)(h + 1) * FF))[lane];
            float4 wr2 = ((const float4*)(W1b_r + (size_t)(h + 2) * FF))[lane];
            float4 wr3 = ((const float4*)(W1b_r + (size_t)(h + 3) * FF))[lane];
            float a0 = dot4(wl0, m) + dot4(wr0, x);
            float a1 = dot4(wl1, m) + dot4(wr1, x);
            float a2 = dot4(wl2, m) + dot4(wr2, x);
            float a3 = dot4(wl3, m) + dot4(wr3, x);
            warp_sum4(a0, a1, a2, a3);
            if (lane == 0) {
                ((float*)hinf4)[h + 0] = fmaxf(a0 + b1b_l[h + 0], 0.0f);
                ((float*)hinf4)[h + 1] = fmaxf(a1 + b1b_l[h + 1], 0.0f);
                ((float*)hinf4)[h + 2] = fmaxf(a2 + b1b_l[h + 2], 0.0f);
                ((float*)hinf4)[h + 3] = fmaxf(a3 + b1b_l[h + 3], 0.0f);
            }
        }
    }
    __syncthreads();

    {
        float4 m0 = meanh4[lane], m1 = meanh4[lane + 32];
        float4 h0 = hinf4[lane],  h1 = hinf4[lane + 32];
        for (int g = wid; g < OO / 2; g += 8) {
            int o = 2 * g;
            const float4* wl0 = (const float4*)(W2b_l + (size_t)(o + 0) * HH);
            const float4* wl1 = (const float4*)(W2b_l + (size_t)(o + 1) * HH);
            const float4* wr0 = (const float4*)(W2b_r + (size_t)(o + 0) * HH);
            const float4* wr1 = (const float4*)(W2b_r + (size_t)(o + 1) * HH);
            float4 a00 = wl0[lane], a01 = wl0[lane + 32];
            float4 a10 = wl1[lane], a11 = wl1[lane + 32];
            float4 b00 = wr0[lane], b01 = wr0[lane + 32];
            float4 b10 = wr1[lane], b11 = wr1[lane + 32];
            float v0 = dot4(a00, m0) + dot4(a01, m1) + dot4(b00, h0) + dot4(b01, h1);
            float v1 = dot4(a10, m0) + dot4(a11, m1) + dot4(b10, h0) + dot4(b11, h1);
            float vz = 0.0f, vw = 0.0f;
            warp_sum4(v0, v1, vz, vw);
            if (lane == 0) {
                g_seq[t][o + 0] = v0 + b2b_l[o + 0];
                g_seq[t][o + 1] = v1 + b2b_l[o + 1];
            }
        }
    }
}

// ---------------- GRU input gates, COALESCED warp-per-row (R8-proven) ----------------
__global__ void k_gi(const float* __restrict__ W_ih, const float* __restrict__ b_ih) {
    int t = blockIdx.y;
    int tid = threadIdx.x;
    int wid = tid >> 5, lane = tid & 31;
    __shared__ float4 xs4[OO / 4];
    if (tid < OO) ((float*)xs4)[tid] = g_seq[t][tid];
    __syncthreads();
    float4 x = xs4[lane];
    int gw = blockIdx.x * 8 + wid;           // 0..95 global warps
    for (int row = gw; row < 3 * HH; row += 96) {
        float4 w = ((const float4*)(W_ih + (size_t)row * OO))[lane];
        float v = w.x * x.x + w.y * x.y + w.z * x.z + w.w * x.w;
        v = warp_sum(v);
        if (lane == 0) g_gi[t][row] = v + b_ih[row];
    }
}

// ---------------- one GRU step: warp per h-row (R1-proven, untouched) ----------------
__global__ void k_gru(int t, const float* __restrict__ W_hh, const float* __restrict__ b_hh) {
    const float* hprev = g_hbuf[t & 1];
    float* hnext = g_hbuf[(t + 1) & 1];
    int gwarp = (blockIdx.x * blockDim.x + threadIdx.x) >> 5;
    int lane = threadIdx.x & 31;
    if (gwarp >= HH) return;
    int w = gwarp;
    float sr = 0.0f, sz = 0.0f, sn = 0.0f;
    const float* wr = W_hh + (size_t)w * HH;
    const float* wz = W_hh + (size_t)(HH + w) * HH;
    const float* wn = W_hh + (size_t)(2 * HH + w) * HH;
    #pragma unroll
    for (int j = 0; j < HH / 32; j++) {
        int k = lane + 32 * j;
        float hv = hprev[k];
        sr += wr[k] * hv;
        sz += wz[k] * hv;
        sn += wn[k] * hv;
    }
    #pragma unroll
    for (int off = 16; off > 0; off >>= 1) {
        sr += __shfl_down_sync(0xffffffffu, sr, off);
        sz += __shfl_down_sync(0xffffffffu, sz, off);
        sn += __shfl_down_sync(0xffffffffu, sn, off);
    }
    if (lane == 0) {
        float gh_r = sr + b_hh[w];
        float gh_z = sz + b_hh[HH + w];
        float gh_n = sn + b_hh[2 * HH + w];
        float gi_r = g_gi[t][w];
        float gi_z = g_gi[t][HH + w];
        float gi_n = g_gi[t][2 * HH + w];
        float r = 1.0f / (1.0f + expf(-(gi_r + gh_r)));
        float z = 1.0f / (1.0f + expf(-(gi_z + gh_z)));
        float nn = tanhf(gi_n + r * gh_n);
        float hn = (1.0f - z) * nn + z * hprev[w];
        hnext[w] = hn;
        g_rnn[t][w] = hn;
    }
}

// ---------------- attention + prediction head (R1-proven, untouched) ----------------
__global__ void k_head(const float* __restrict__ W_att, const float* __restrict__ b_att,
                       const float* __restrict__ W_p1, const float* __restrict__ b_p1,
                       const float* __restrict__ W_p2, const float* __restrict__ b_p2,
                       float* __restrict__ out) {
    __shared__ float att[TT], ctx[HH], red[HH];
    int tid = threadIdx.x;
    if (tid < TT) {
        float lg = b_att[0];
        for (int h = 0; h < HH; h++) lg += g_rnn[tid][h] * W_att[h];
        att[tid] = lg;
    }
    __syncthreads();
    if (tid == 0) {
        float m = att[0];
        for (int t = 1; t < TT; t++) m = fmaxf(m, att[t]);
        float s = 0.0f;
        for (int t = 0; t < TT; t++) { att[t] = expf(att[t] - m); s += att[t]; }
        for (int t = 0; t < TT; t++) att[t] /= s;
    }
    __syncthreads();
    {
        float c = 0.0f;
        #pragma unroll
        for (int t = 0; t < TT; t++) c += att[t] * g_rnn[t][tid];
        ctx[tid] = c;
    }
    __syncthreads();
    if (tid < HH / 2) {
        float v = b_p1[tid];
        const float* w = W_p1 + (size_t)tid * HH;
        #pragma unroll 8
        for (int h = 0; h < HH; h++) v += w[h] * ctx[h];
        v = fmaxf(v, 0.0f);
        red[tid] = v * W_p2[tid];
    }
    __syncthreads();
    if (tid == 0) {
        float s = b_p2[0];
        for (int j = 0; j < HH / 2; j++) s += red[j];
        out[0] = s;
    }
}

extern "C" void kernel_launch(void* const* d_in, const int* in_sizes, int n_in,
                              void* d_out, int out_size) {
    const float* x_inf  = (const float*)d_in[0];
    const float* x_item = (const float*)d_in[1];
    const int*   e1s    = (const int*)d_in[2];
    const int*   e1d    = (const int*)d_in[3];
    const int*   e2s    = (const int*)d_in[4];
    const int*   e2d    = (const int*)d_in[5];
    const int*   tgt    = (const int*)d_in[6];
    const float* W1a_l  = (const float*)d_in[7];
    const float* b1a_l  = (const float*)d_in[8];
    const float* W1a_r  = (const float*)d_in[9];
    const float* W1b_l  = (const float*)d_in[10];
    const float* b1b_l  = (const float*)d_in[11];
    const float* W1b_r  = (const float*)d_in[12];
    // d_in[13..15]: W2a_* (dead code in reference — o_item unused)
    const float* W2b_l  = (const float*)d_in[16];
    const float* b2b_l  = (const float*)d_in[17];
    const float* W2b_r  = (const float*)d_in[18];
    const float* W_ih   = (const float*)d_in[19];
    const float* W_hh   = (const float*)d_in[20];
    const float* b_ih   = (const float*)d_in[21];
    const float* b_hh   = (const float*)d_in[22];
    const float* W_att  = (const float*)d_in[23];
    const float* b_att  = (const float*)d_in[24];
    const float* W_p1   = (const float*)d_in[25];
    const float* b_p1   = (const float*)d_in[26];
    const float* W_p2   = (const float*)d_in[27];
    const float* b_p2   = (const float*)d_in[28];
    float* out = (float*)d_out;

    k_init<<<2048, 256>>>();
    dim3 gscan(SCAN_BLK, TT);
    k_scan_e2<<<gscan, 256>>>(e2s, e2d, x_item, tgt);
    k_assign<<<TT, 256>>>();
    k_scan_e1<<<gscan, 256>>>(e1s, e1d, x_inf);
    k_hitem<<<dim3(64, TT), 256>>>(x_item, W1a_l, b1a_l, W1a_r);
    k_oinf<<<TT, 256>>>(x_inf, W1b_l, b1b_l, W1b_r, W2b_l, b2b_l, W2b_r, tgt);
    k_gi<<<dim3(12, TT), 256>>>(W_ih, b_ih);
    for (int t = 0; t < TT; t++)
        k_gru<<<32, 256>>>(t, W_hh, b_hh);
    k_head<<<1, 256>>>(W_att, b_att, W_p1, b_p1, W_p2, b_p2, out);
}

// round 14
// speedup vs baseline: 1.3846x; 1.3846x over previous
#include <cuda_runtime.h>
#include <math.h>

#define TT 8
#define NI 20000
#define NK 50000
#define FF 128
#define HH 256
#define OO 128
#define EE 500000
#define MAXS 512
#define NKW ((NK + 31) / 32)        // 1563 bitmap words
#define SCAN_BLK 123                 // ceil((EE/4) / (4*256))
#define SCAN_STRIDE (SCAN_BLK * 256)
#define FULLW 0xffffffffu

// ---------------- scratch (device globals; no allocation allowed) ----------------
__device__ int      g_item_flag[TT][NK];   // -1 empty, -2 marked, >=0 slot
__device__ int      g_item_mult[TT][NK];   // edge multiplicity (src,target) in e2
__device__ unsigned g_bitmap[TT][NKW];     // 1 bit per slotted item
__device__ int      g_item_id[TT][MAXS];
__device__ int      g_item_cnt[TT][MAXS];  // e1 in-degree of needed item
__device__ float    g_item_acc[TT][MAXS][FF];
__device__ float    g_hitem[TT][MAXS][HH];
__device__ int      g_num_items[TT];
__device__ float    g_accx[TT][FF];        // sum of x_item over target's e2 edges
__device__ int      g_edge_cnt[TT];
__device__ float    g_seq[TT][OO];
__device__ float    g_gi[TT][3 * HH];
__device__ float    g_hbuf[2][HH];
__device__ float    g_rnn[TT][HH];

// ---------------- init / reset (R11-proven) ----------------
__global__ void k_init() {
    int idx = blockIdx.x * blockDim.x + threadIdx.x;
    if (idx < TT * NK) {
        ((int*)g_item_flag)[idx] = -1;
        ((int*)g_item_mult)[idx] = 0;
    }
    if (idx < TT * MAXS * FF) ((float*)g_item_acc)[idx] = 0.0f;
    if (idx < TT * MAXS)      ((int*)g_item_cnt)[idx] = 0;
    if (idx < TT * FF)        ((float*)g_accx)[idx] = 0.0f;
    if (idx < TT * NKW)       ((unsigned*)g_bitmap)[idx] = 0u;
    if (idx < TT) { g_edge_cnt[idx] = 0; g_num_items[idx] = 0; }
    if (idx < 2 * HH) ((float*)g_hbuf)[idx] = 0.0f;
}

// ---------------- pass A: scan e2, warp-cooperative hit path (R11-proven) ----------------
__global__ void k_scan_e2(const int* __restrict__ e2s, const int* __restrict__ e2d,
                          const float* __restrict__ x_item, const int* __restrict__ tgtp) {
    int t = blockIdx.y;
    int tgt = *tgtp;
    const int4* d4 = (const int4*)(e2d + (size_t)t * EE);
    const int* s = e2s + (size_t)t * EE;
    int lane = threadIdx.x & 31;
    int tidx = blockIdx.x * blockDim.x + threadIdx.x;
    int4 v[4]; int ok[4];
    #pragma unroll
    for (int k = 0; k < 4; k++) {
        int idx = tidx + k * SCAN_STRIDE;
        ok[k] = idx < EE / 4;
        v[k] = ok[k] ? __ldg(d4 + idx) : make_int4(-1, -1, -1, -1);
    }
    #pragma unroll
    for (int k = 0; k < 4; k++) {
        int e = 4 * (tidx + k * SCAN_STRIDE);
        #pragma unroll
        for (int j = 0; j < 4; j++) {
            int dv = (j == 0) ? v[k].x : (j == 1) ? v[k].y : (j == 2) ? v[k].z : v[k].w;
            bool hit = ok[k] && (dv == tgt);
            unsigned m = __ballot_sync(FULLW, hit);
            while (m) {
                int ldr = __ffs(m) - 1;
                m &= m - 1;
                int eb = __shfl_sync(FULLW, e + j, ldr);
                int src = 0;
                if (lane == ldr) src = s[eb];
                src = __shfl_sync(FULLW, src, ldr);
                if (lane == 0) {
                    atomicAdd(&g_edge_cnt[t], 1);
                    atomicAdd(&g_item_mult[t][src], 1);
                    int old = atomicExch(&g_item_flag[t][src], -2);
                    if (old == -1) {
                        int sl = atomicAdd(&g_num_items[t], 1);
                        if (sl < MAXS) g_item_id[t][sl] = src;
                    }
                }
                float4 xv = ((const float4*)(x_item + ((size_t)t * NK + src) * FF))[lane];
                atomicAdd(&g_accx[t][4 * lane + 0], xv.x);
                atomicAdd(&g_accx[t][4 * lane + 1], xv.y);
                atomicAdd(&g_accx[t][4 * lane + 2], xv.z);
                atomicAdd(&g_accx[t][4 * lane + 3], xv.w);
            }
        }
    }
}

// ---------------- pass A2: assign slot ids + build bitmap (R11-proven) ----------------
__global__ void k_assign() {
    int t = blockIdx.x;
    if (threadIdx.x == 0 && g_num_items[t] > MAXS) g_num_items[t] = MAXS;
    __syncthreads();
    int n = g_num_items[t];
    for (int k = threadIdx.x; k < n; k += blockDim.x) {
        int id = g_item_id[t][k];
        g_item_flag[t][id] = k;
        atomicOr(&g_bitmap[t][id >> 5], 1u << (id & 31));
    }
}

// ---------------- pass B: scan e1, bitmap + warp-cooperative hit path (R11-proven) ----------------
__global__ void k_scan_e1(const int* __restrict__ e1s, const int* __restrict__ e1d,
                          const float* __restrict__ x_inf) {
    int t = blockIdx.y;
    __shared__ unsigned bm[NKW];
    for (int w = threadIdx.x; w < NKW; w += blockDim.x) bm[w] = g_bitmap[t][w];
    __syncthreads();
    const int4* d4 = (const int4*)(e1d + (size_t)t * EE);
    const int* s = e1s + (size_t)t * EE;
    const int* flag = g_item_flag[t];
    int lane = threadIdx.x & 31;
    int tidx = blockIdx.x * blockDim.x + threadIdx.x;
    int4 v[4]; int ok[4];
    #pragma unroll
    for (int k = 0; k < 4; k++) {
        int idx = tidx + k * SCAN_STRIDE;
        ok[k] = idx < EE / 4;
        v[k] = ok[k] ? __ldg(d4 + idx) : make_int4(0, 0, 0, 0);
    }
    #pragma unroll
    for (int k = 0; k < 4; k++) {
        int e = 4 * (tidx + k * SCAN_STRIDE);
        #pragma unroll
        for (int j = 0; j < 4; j++) {
            int dv = (j == 0) ? v[k].x : (j == 1) ? v[k].y : (j == 2) ? v[k].z : v[k].w;
            int sl = -1;
            if (ok[k] && ((bm[dv >> 5] >> (dv & 31)) & 1u)) sl = flag[dv];
            bool hit = sl >= 0;
            unsigned m = __ballot_sync(FULLW, hit);
            while (m) {
                int ldr = __ffs(m) - 1;
                m &= m - 1;
                int slb = __shfl_sync(FULLW, sl, ldr);
                int eb = __shfl_sync(FULLW, e + j, ldr);
                int src = 0;
                if (lane == ldr) src = s[eb];
                src = __shfl_sync(FULLW, src, ldr);
                if (lane == 0) atomicAdd(&g_item_cnt[t][slb], 1);
                float4 xv = ((const float4*)(x_inf + ((size_t)t * NI + src) * FF))[lane];
                atomicAdd(&g_item_acc[t][slb][4 * lane + 0], xv.x);
                atomicAdd(&g_item_acc[t][slb][4 * lane + 1], xv.y);
                atomicAdd(&g_item_acc[t][slb][4 * lane + 2], xv.z);
                atomicAdd(&g_item_acc[t][slb][4 * lane + 3], xv.w);
            }
        }
    }
}

__device__ __forceinline__ float warp_sum(float v) {
    #pragma unroll
    for (int off = 16; off > 0; off >>= 1) v += __shfl_down_sync(0xffffffffu, v, off);
    return v;
}

// ---------------- pass C: h_item — R8 inner code, 8x more blocks (row bands) ----------------
// grid = (64 slot-stride, 8 row-bands, TT); each block computes a 32-row band of one slot.
__global__ void k_hitem(const float* __restrict__ x_item,
                        const float* __restrict__ W1a_l, const float* __restrict__ b1a_l,
                        const float* __restrict__ W1a_r) {
    int t = blockIdx.z;
    int band = blockIdx.y;               // 0..7 -> rows [band*32, band*32+32)
    int tid = threadIdx.x;
    int wid = tid >> 5, lane = tid & 31;
    __shared__ float4 mean4[FF / 4], xrow4[FF / 4];
    for (int sl = blockIdx.x; sl < g_num_items[t]; sl += gridDim.x) {
        int id = g_item_id[t][sl];
        float c = fmaxf((float)g_item_cnt[t][sl], 1.0f);
        if (tid < FF) {
            ((float*)mean4)[tid] = g_item_acc[t][sl][tid] / c;
            ((float*)xrow4)[tid] = x_item[((size_t)t * NK + id) * FF + tid];
        }
        __syncthreads();
        float4 m = mean4[lane], x = xrow4[lane];
        // 8 warps x 4 rows = this block's 32-row band
        #pragma unroll
        for (int r = 0; r < 4; r++) {
            int h = band * 32 + wid * 4 + r;
            float4 wl = ((const float4*)(W1a_l + (size_t)h * FF))[lane];
            float4 wr = ((const float4*)(W1a_r + (size_t)h * FF))[lane];
            float a = wl.x * m.x + wl.y * m.y + wl.z * m.z + wl.w * m.w
                    + wr.x * x.x + wr.y * x.y + wr.z * x.z + wr.w * x.w;
            a = warp_sum(a);
            if (lane == 0) g_hitem[t][sl][h] = fmaxf(a + b1a_l[h], 0.0f);
        }
        __syncthreads();
    }
}

// ---------------- pass D: h_inf[target] + o_inf[target], COALESCED (R8-proven) ----------------
__global__ void k_oinf(const float* __restrict__ x_inf,
                       const float* __restrict__ W1b_l, const float* __restrict__ b1b_l,
                       const float* __restrict__ W1b_r,
                       const float* __restrict__ W2b_l, const float* __restrict__ b2b_l,
                       const float* __restrict__ W2b_r,
                       const int* __restrict__ tgtp) {
    int t = blockIdx.x;
    int tid = threadIdx.x;
    int wid = tid >> 5, lane = tid & 31;
    int tgt = *tgtp;
    __shared__ float4 meanx4[FF / 4], xt4[FF / 4];
    __shared__ float4 hinf4[HH / 4], meanh4[HH / 4];
    __shared__ float multw[MAXS];
    float ec = fmaxf((float)g_edge_cnt[t], 1.0f);
    int n = g_num_items[t];
    if (n > MAXS) n = MAXS;
    if (tid < FF) {
        ((float*)meanx4)[tid] = g_accx[t][tid] / ec;
        ((float*)xt4)[tid]    = x_inf[((size_t)t * NI + tgt) * FF + tid];
    }
    for (int k = tid; k < n; k += blockDim.x)
        multw[k] = (float)g_item_mult[t][g_item_id[t][k]];
    __syncthreads();

    {
        float mh = 0.0f;
        for (int k = 0; k < n; k++) mh += multw[k] * g_hitem[t][k][tid];
        ((float*)meanh4)[tid] = mh / ec;
    }
    {
        float4 m = meanx4[lane], x = xt4[lane];
        for (int h = wid; h < HH; h += 8) {
            float4 wl = ((const float4*)(W1b_l + (size_t)h * FF))[lane];
            float4 wr = ((const float4*)(W1b_r + (size_t)h * FF))[lane];
            float a = wl.x * m.x + wl.y * m.y + wl.z * m.z + wl.w * m.w
                    + wr.x * x.x + wr.y * x.y + wr.z * x.z + wr.w * x.w;
            a = warp_sum(a);
            if (lane == 0) ((float*)hinf4)[h] = fmaxf(a + b1b_l[h], 0.0f);
        }
    }
    __syncthreads();

    {
        float4 m0 = meanh4[lane], m1 = meanh4[lane + 32];
        float4 h0 = hinf4[lane],  h1 = hinf4[lane + 32];
        for (int o = wid; o < OO; o += 8) {
            const float4* wl = (const float4*)(W2b_l + (size_t)o * HH);
            const float4* wr = (const float4*)(W2b_r + (size_t)o * HH);
            float4 a0 = wl[lane], a1 = wl[lane + 32];
            float4 b0 = wr[lane], b1 = wr[lane + 32];
            float v = a0.x * m0.x + a0.y * m0.y + a0.z * m0.z + a0.w * m0.w
                    + a1.x * m1.x + a1.y * m1.y + a1.z * m1.z + a1.w * m1.w
                    + b0.x * h0.x + b0.y * h0.y + b0.z * h0.z + b0.w * h0.w
                    + b1.x * h1.x + b1.y * h1.y + b1.z * h1.z + b1.w * h1.w;
            v = warp_sum(v);
            if (lane == 0) g_seq[t][o] = v + b2b_l[o];
        }
    }
}

// ---------------- GRU input gates, COALESCED warp-per-row (R8-proven) ----------------
__global__ void k_gi(const float* __restrict__ W_ih, const float* __restrict__ b_ih) {
    int t = blockIdx.y;
    int tid = threadIdx.x;
    int wid = tid >> 5, lane = tid & 31;
    __shared__ float4 xs4[OO / 4];
    if (tid < OO) ((float*)xs4)[tid] = g_seq[t][tid];
    __syncthreads();
    float4 x = xs4[lane];
    int gw = blockIdx.x * 8 + wid;           // 0..95 global warps
    for (int row = gw; row < 3 * HH; row += 96) {
        float4 w = ((const float4*)(W_ih + (size_t)row * OO))[lane];
        float v = w.x * x.x + w.y * x.y + w.z * x.z + w.w * x.w;
        v = warp_sum(v);
        if (lane == 0) g_gi[t][row] = v + b_ih[row];
    }
}

// ---------------- one GRU step: warp per h-row (R1-proven, untouched) ----------------
__global__ void k_gru(int t, const float* __restrict__ W_hh, const float* __restrict__ b_hh) {
    const float* hprev = g_hbuf[t & 1];
    float* hnext = g_hbuf[(t + 1) & 1];
    int gwarp = (blockIdx.x * blockDim.x + threadIdx.x) >> 5;
    int lane = threadIdx.x & 31;
    if (gwarp >= HH) return;
    int w = gwarp;
    float sr = 0.0f, sz = 0.0f, sn = 0.0f;
    const float* wr = W_hh + (size_t)w * HH;
    const float* wz = W_hh + (size_t)(HH + w) * HH;
    const float* wn = W_hh + (size_t)(2 * HH + w) * HH;
    #pragma unroll
    for (int j = 0; j < HH / 32; j++) {
        int k = lane + 32 * j;
        float hv = hprev[k];
        sr += wr[k] * hv;
        sz += wz[k] * hv;
        sn += wn[k] * hv;
    }
    #pragma unroll
    for (int off = 16; off > 0; off >>= 1) {
        sr += __shfl_down_sync(0xffffffffu, sr, off);
        sz += __shfl_down_sync(0xffffffffu, sz, off);
        sn += __shfl_down_sync(0xffffffffu, sn, off);
    }
    if (lane == 0) {
        float gh_r = sr + b_hh[w];
        float gh_z = sz + b_hh[HH + w];
        float gh_n = sn + b_hh[2 * HH + w];
        float gi_r = g_gi[t][w];
        float gi_z = g_gi[t][HH + w];
        float gi_n = g_gi[t][2 * HH + w];
        float r = 1.0f / (1.0f + expf(-(gi_r + gh_r)));
        float z = 1.0f / (1.0f + expf(-(gi_z + gh_z)));
        float nn = tanhf(gi_n + r * gh_n);
        float hn = (1.0f - z) * nn + z * hprev[w];
        hnext[w] = hn;
        g_rnn[t][w] = hn;
    }
}

// ---------------- attention + prediction head (R1-proven, untouched) ----------------
__global__ void k_head(const float* __restrict__ W_att, const float* __restrict__ b_att,
                       const float* __restrict__ W_p1, const float* __restrict__ b_p1,
                       const float* __restrict__ W_p2, const float* __restrict__ b_p2,
                       float* __restrict__ out) {
    __shared__ float att[TT], ctx[HH], red[HH];
    int tid = threadIdx.x;
    if (tid < TT) {
        float lg = b_att[0];
        for (int h = 0; h < HH; h++) lg += g_rnn[tid][h] * W_att[h];
        att[tid] = lg;
    }
    __syncthreads();
    if (tid == 0) {
        float m = att[0];
        for (int t = 1; t < TT; t++) m = fmaxf(m, att[t]);
        float s = 0.0f;
        for (int t = 0; t < TT; t++) { att[t] = expf(att[t] - m); s += att[t]; }
        for (int t = 0; t < TT; t++) att[t] /= s;
    }
    __syncthreads();
    {
        float c = 0.0f;
        #pragma unroll
        for (int t = 0; t < TT; t++) c += att[t] * g_rnn[t][tid];
        ctx[tid] = c;
    }
    __syncthreads();
    if (tid < HH / 2) {
        float v = b_p1[tid];
        const float* w = W_p1 + (size_t)tid * HH;
        #pragma unroll 8
        for (int h = 0; h < HH; h++) v += w[h] * ctx[h];
        v = fmaxf(v, 0.0f);
        red[tid] = v * W_p2[tid];
    }
    __syncthreads();
    if (tid == 0) {
        float s = b_p2[0];
        for (int j = 0; j < HH / 2; j++) s += red[j];
        out[0] = s;
    }
}

extern "C" void kernel_launch(void* const* d_in, const int* in_sizes, int n_in,
                              void* d_out, int out_size) {
    const float* x_inf  = (const float*)d_in[0];
    const float* x_item = (const float*)d_in[1];
    const int*   e1s    = (const int*)d_in[2];
    const int*   e1d    = (const int*)d_in[3];
    const int*   e2s    = (const int*)d_in[4];
    const int*   e2d    = (const int*)d_in[5];
    const int*   tgt    = (const int*)d_in[6];
    const float* W1a_l  = (const float*)d_in[7];
    const float* b1a_l  = (const float*)d_in[8];
    const float* W1a_r  = (const float*)d_in[9];
    const float* W1b_l  = (const float*)d_in[10];
    const float* b1b_l  = (const float*)d_in[11];
    const float* W1b_r  = (const float*)d_in[12];
    // d_in[13..15]: W2a_* (dead code in reference — o_item unused)
    const float* W2b_l  = (const float*)d_in[16];
    const float* b2b_l  = (const float*)d_in[17];
    const float* W2b_r  = (const float*)d_in[18];
    const float* W_ih   = (const float*)d_in[19];
    const float* W_hh   = (const float*)d_in[20];
    const float* b_ih   = (const float*)d_in[21];
    const float* b_hh   = (const float*)d_in[22];
    const float* W_att  = (const float*)d_in[23];
    const float* b_att  = (const float*)d_in[24];
    const float* W_p1   = (const float*)d_in[25];
    const float* b_p1   = (const float*)d_in[26];
    const float* W_p2   = (const float*)d_in[27];
    const float* b_p2   = (const float*)d_in[28];
    float* out = (float*)d_out;

    k_init<<<2048, 256>>>();
    dim3 gscan(SCAN_BLK, TT);
    k_scan_e2<<<gscan, 256>>>(e2s, e2d, x_item, tgt);
    k_assign<<<TT, 256>>>();
    k_scan_e1<<<gscan, 256>>>(e1s, e1d, x_inf);
    k_hitem<<<dim3(64, 8, TT), 256>>>(x_item, W1a_l, b1a_l, W1a_r);
    k_oinf<<<TT, 256>>>(x_inf, W1b_l, b1b_l, W1b_r, W2b_l, b2b_l, W2b_r, tgt);
    k_gi<<<dim3(12, TT), 256>>>(W_ih, b_ih);
    for (int t = 0; t < TT; t++)
        k_gru<<<32, 256>>>(t, W_hh, b_hh);
    k_head<<<1, 256>>>(W_att, b_att, W_p1, b_p1, W_p2, b_p2, out);
}

// round 15
// speedup vs baseline: 1.3981x; 1.0097x over previous
#include <cuda_runtime.h>
#include <math.h>

#define TT 8
#define NI 20000
#define NK 50000
#define FF 128
#define HH 256
#define OO 128
#define EE 500000
#define MAXS 512
#define NKW ((NK + 31) / 32)        // 1563 bitmap words
#define SCAN_BLK 123                 // ceil((EE/4) / (4*256))
#define SCAN_STRIDE (SCAN_BLK * 256)
#define FULLW 0xffffffffu

// ---------------- scratch (device globals; no allocation allowed) ----------------
__device__ int      g_item_flag[TT][NK];   // -1 empty, -2 marked, >=0 slot
__device__ int      g_item_mult[TT][NK];   // edge multiplicity (src,target) in e2
__device__ unsigned g_bitmap[TT][NKW];     // 1 bit per slotted item
__device__ int      g_item_id[TT][MAXS];
__device__ int      g_item_cnt[TT][MAXS];  // e1 in-degree of needed item
__device__ float    g_item_acc[TT][MAXS][FF];
__device__ float    g_hitem[TT][MAXS][HH];
__device__ int      g_num_items[TT];
__device__ float    g_accx[TT][FF];        // sum of x_item over target's e2 edges
__device__ int      g_edge_cnt[TT];
__device__ float    g_seq[TT][OO];
__device__ float    g_gi[TT][3 * HH];
__device__ float    g_hbuf[2][HH];
__device__ float    g_rnn[TT][HH];

// ---------------- init / reset (R11-proven) ----------------
__global__ void k_init() {
    int idx = blockIdx.x * blockDim.x + threadIdx.x;
    if (idx < TT * NK) {
        ((int*)g_item_flag)[idx] = -1;
        ((int*)g_item_mult)[idx] = 0;
    }
    if (idx < TT * MAXS * FF) ((float*)g_item_acc)[idx] = 0.0f;
    if (idx < TT * MAXS)      ((int*)g_item_cnt)[idx] = 0;
    if (idx < TT * FF)        ((float*)g_accx)[idx] = 0.0f;
    if (idx < TT * NKW)       ((unsigned*)g_bitmap)[idx] = 0u;
    if (idx < TT) { g_edge_cnt[idx] = 0; g_num_items[idx] = 0; }
    if (idx < 2 * HH) ((float*)g_hbuf)[idx] = 0.0f;
}

// ---------------- pass A: scan e2, ONE ballot per int4 + warp-coop hits ----------------
__global__ void k_scan_e2(const int* __restrict__ e2s, const int* __restrict__ e2d,
                          const float* __restrict__ x_item, const int* __restrict__ tgtp) {
    int t = blockIdx.y;
    int tgt = *tgtp;
    const int4* d4 = (const int4*)(e2d + (size_t)t * EE);
    const int* s = e2s + (size_t)t * EE;
    int lane = threadIdx.x & 31;
    int tidx = blockIdx.x * blockDim.x + threadIdx.x;
    int4 v[4]; int ok[4];
    #pragma unroll
    for (int k = 0; k < 4; k++) {
        int idx = tidx + k * SCAN_STRIDE;
        ok[k] = idx < EE / 4;
        v[k] = ok[k] ? __ldg(d4 + idx) : make_int4(-1, -1, -1, -1);
    }
    #pragma unroll
    for (int k = 0; k < 4; k++) {
        int e = 4 * (tidx + k * SCAN_STRIDE);
        int4 vv = v[k];
        unsigned hm = 0u;
        if (ok[k]) {
            hm = (vv.x == tgt ? 1u : 0u) | (vv.y == tgt ? 2u : 0u)
               | (vv.z == tgt ? 4u : 0u) | (vv.w == tgt ? 8u : 0u);
        }
        unsigned m = __ballot_sync(FULLW, hm != 0u);
        while (m) {
            int ldr = __ffs(m) - 1;
            m &= m - 1;
            unsigned lhm = __shfl_sync(FULLW, hm, ldr);
            int le = __shfl_sync(FULLW, e, ldr);
            #pragma unroll
            for (int jj = 0; jj < 4; jj++) {
                if ((lhm >> jj) & 1u) {
                    int src = __ldg(s + le + jj);        // uniform broadcast load
                    if (lane == 0) {
                        atomicAdd(&g_edge_cnt[t], 1);
                        atomicAdd(&g_item_mult[t][src], 1);
                        int old = atomicExch(&g_item_flag[t][src], -2);
                        if (old == -1) {
                            int sl = atomicAdd(&g_num_items[t], 1);
                            if (sl < MAXS) g_item_id[t][sl] = src;
                        }
                    }
                    float4 xv = ((const float4*)(x_item + ((size_t)t * NK + src) * FF))[lane];
                    atomicAdd(&g_accx[t][4 * lane + 0], xv.x);
                    atomicAdd(&g_accx[t][4 * lane + 1], xv.y);
                    atomicAdd(&g_accx[t][4 * lane + 2], xv.z);
                    atomicAdd(&g_accx[t][4 * lane + 3], xv.w);
                }
            }
        }
    }
}

// ---------------- pass A2: assign slot ids + build bitmap (R11-proven) ----------------
__global__ void k_assign() {
    int t = blockIdx.x;
    if (threadIdx.x == 0 && g_num_items[t] > MAXS) g_num_items[t] = MAXS;
    __syncthreads();
    int n = g_num_items[t];
    for (int k = threadIdx.x; k < n; k += blockDim.x) {
        int id = g_item_id[t][k];
        g_item_flag[t][id] = k;
        atomicOr(&g_bitmap[t][id >> 5], 1u << (id & 31));
    }
}

// ---------------- pass B: scan e1, bitmap + ONE ballot per int4 ----------------
__global__ void k_scan_e1(const int* __restrict__ e1s, const int* __restrict__ e1d,
                          const float* __restrict__ x_inf) {
    int t = blockIdx.y;
    __shared__ unsigned bm[NKW];
    for (int w = threadIdx.x; w < NKW; w += blockDim.x) bm[w] = g_bitmap[t][w];
    __syncthreads();
    const int4* d4 = (const int4*)(e1d + (size_t)t * EE);
    const int* s = e1s + (size_t)t * EE;
    const int* flag = g_item_flag[t];
    int lane = threadIdx.x & 31;
    int tidx = blockIdx.x * blockDim.x + threadIdx.x;
    int4 v[4]; int ok[4];
    #pragma unroll
    for (int k = 0; k < 4; k++) {
        int idx = tidx + k * SCAN_STRIDE;
        ok[k] = idx < EE / 4;
        v[k] = ok[k] ? __ldg(d4 + idx) : make_int4(0, 0, 0, 0);
    }
    #pragma unroll
    for (int k = 0; k < 4; k++) {
        int e = 4 * (tidx + k * SCAN_STRIDE);
        int4 vv = v[k];
        unsigned hm = 0u;
        if (ok[k]) {
            hm = (((bm[vv.x >> 5] >> (vv.x & 31)) & 1u) ? 1u : 0u)
               | (((bm[vv.y >> 5] >> (vv.y & 31)) & 1u) ? 2u : 0u)
               | (((bm[vv.z >> 5] >> (vv.z & 31)) & 1u) ? 4u : 0u)
               | (((bm[vv.w >> 5] >> (vv.w & 31)) & 1u) ? 8u : 0u);
        }
        unsigned m = __ballot_sync(FULLW, hm != 0u);
        while (m) {
            int ldr = __ffs(m) - 1;
            m &= m - 1;
            unsigned lhm = __shfl_sync(FULLW, hm, ldr);
            int le = __shfl_sync(FULLW, e, ldr);
            int lvx = __shfl_sync(FULLW, vv.x, ldr);
            int lvy = __shfl_sync(FULLW, vv.y, ldr);
            int lvz = __shfl_sync(FULLW, vv.z, ldr);
            int lvw = __shfl_sync(FULLW, vv.w, ldr);
            #pragma unroll
            for (int jj = 0; jj < 4; jj++) {
                if ((lhm >> jj) & 1u) {
                    int dv = (jj == 0) ? lvx : (jj == 1) ? lvy : (jj == 2) ? lvz : lvw;
                    int slb = __ldg(flag + dv);          // uniform broadcast load
                    if (slb < 0) continue;               // bitmap false-positive guard (shouldn't happen)
                    int src = __ldg(s + le + jj);        // uniform broadcast load
                    if (lane == 0) atomicAdd(&g_item_cnt[t][slb], 1);
                    float4 xv = ((const float4*)(x_inf + ((size_t)t * NI + src) * FF))[lane];
                    atomicAdd(&g_item_acc[t][slb][4 * lane + 0], xv.x);
                    atomicAdd(&g_item_acc[t][slb][4 * lane + 1], xv.y);
                    atomicAdd(&g_item_acc[t][slb][4 * lane + 2], xv.z);
                    atomicAdd(&g_item_acc[t][slb][4 * lane + 3], xv.w);
                }
            }
        }
    }
}

__device__ __forceinline__ float warp_sum(float v) {
    #pragma unroll
    for (int off = 16; off > 0; off >>= 1) v += __shfl_down_sync(0xffffffffu, v, off);
    return v;
}

// ---------------- pass C: h_item — row-banded (R14-proven) ----------------
__global__ void k_hitem(const float* __restrict__ x_item,
                        const float* __restrict__ W1a_l, const float* __restrict__ b1a_l,
                        const float* __restrict__ W1a_r) {
    int t = blockIdx.z;
    int band = blockIdx.y;               // 0..7 -> rows [band*32, band*32+32)
    int tid = threadIdx.x;
    int wid = tid >> 5, lane = tid & 31;
    __shared__ float4 mean4[FF / 4], xrow4[FF / 4];
    for (int sl = blockIdx.x; sl < g_num_items[t]; sl += gridDim.x) {
        int id = g_item_id[t][sl];
        float c = fmaxf((float)g_item_cnt[t][sl], 1.0f);
        if (tid < FF) {
            ((float*)mean4)[tid] = g_item_acc[t][sl][tid] / c;
            ((float*)xrow4)[tid] = x_item[((size_t)t * NK + id) * FF + tid];
        }
        __syncthreads();
        float4 m = mean4[lane], x = xrow4[lane];
        #pragma unroll
        for (int r = 0; r < 4; r++) {
            int h = band * 32 + wid * 4 + r;
            float4 wl = ((const float4*)(W1a_l + (size_t)h * FF))[lane];
            float4 wr = ((const float4*)(W1a_r + (size_t)h * FF))[lane];
            float a = wl.x * m.x + wl.y * m.y + wl.z * m.z + wl.w * m.w
                    + wr.x * x.x + wr.y * x.y + wr.z * x.z + wr.w * x.w;
            a = warp_sum(a);
            if (lane == 0) g_hitem[t][sl][h] = fmaxf(a + b1a_l[h], 0.0f);
        }
        __syncthreads();
    }
}

// ---------------- pass D: h_inf[target] + o_inf[target], COALESCED (R8-proven) ----------------
__global__ void k_oinf(const float* __restrict__ x_inf,
                       const float* __restrict__ W1b_l, const float* __restrict__ b1b_l,
                       const float* __restrict__ W1b_r,
                       const float* __restrict__ W2b_l, const float* __restrict__ b2b_l,
                       const float* __restrict__ W2b_r,
                       const int* __restrict__ tgtp) {
    int t = blockIdx.x;
    int tid = threadIdx.x;
    int wid = tid >> 5, lane = tid & 31;
    int tgt = *tgtp;
    __shared__ float4 meanx4[FF / 4], xt4[FF / 4];
    __shared__ float4 hinf4[HH / 4], meanh4[HH / 4];
    __shared__ float multw[MAXS];
    float ec = fmaxf((float)g_edge_cnt[t], 1.0f);
    int n = g_num_items[t];
    if (n > MAXS) n = MAXS;
    if (tid < FF) {
        ((float*)meanx4)[tid] = g_accx[t][tid] / ec;
        ((float*)xt4)[tid]    = x_inf[((size_t)t * NI + tgt) * FF + tid];
    }
    for (int k = tid; k < n; k += blockDim.x)
        multw[k] = (float)g_item_mult[t][g_item_id[t][k]];
    __syncthreads();

    {
        float mh = 0.0f;
        for (int k = 0; k < n; k++) mh += multw[k] * g_hitem[t][k][tid];
        ((float*)meanh4)[tid] = mh / ec;
    }
    {
        float4 m = meanx4[lane], x = xt4[lane];
        for (int h = wid; h < HH; h += 8) {
            float4 wl = ((const float4*)(W1b_l + (size_t)h * FF))[lane];
            float4 wr = ((const float4*)(W1b_r + (size_t)h * FF))[lane];
            float a = wl.x * m.x + wl.y * m.y + wl.z * m.z + wl.w * m.w
                    + wr.x * x.x + wr.y * x.y + wr.z * x.z + wr.w * x.w;
            a = warp_sum(a);
            if (lane == 0) ((float*)hinf4)[h] = fmaxf(a + b1b_l[h], 0.0f);
        }
    }
    __syncthreads();

    {
        float4 m0 = meanh4[lane], m1 = meanh4[lane + 32];
        float4 h0 = hinf4[lane],  h1 = hinf4[lane + 32];
        for (int o = wid; o < OO; o += 8) {
            const float4* wl = (const float4*)(W2b_l + (size_t)o * HH);
            const float4* wr = (const float4*)(W2b_r + (size_t)o * HH);
            float4 a0 = wl[lane], a1 = wl[lane + 32];
            float4 b0 = wr[lane], b1 = wr[lane + 32];
            float v = a0.x * m0.x + a0.y * m0.y + a0.z * m0.z + a0.w * m0.w
                    + a1.x * m1.x + a1.y * m1.y + a1.z * m1.z + a1.w * m1.w
                    + b0.x * h0.x + b0.y * h0.y + b0.z * h0.z + b0.w * h0.w
                    + b1.x * h1.x + b1.y * h1.y + b1.z * h1.z + b1.w * h1.w;
            v = warp_sum(v);
            if (lane == 0) g_seq[t][o] = v + b2b_l[o];
        }
    }
}

// ---------------- GRU input gates, COALESCED warp-per-row (R8-proven) ----------------
__global__ void k_gi(const float* __restrict__ W_ih, const float* __restrict__ b_ih) {
    int t = blockIdx.y;
    int tid = threadIdx.x;
    int wid = tid >> 5, lane = tid & 31;
    __shared__ float4 xs4[OO / 4];
    if (tid < OO) ((float*)xs4)[tid] = g_seq[t][tid];
    __syncthreads();
    float4 x = xs4[lane];
    int gw = blockIdx.x * 8 + wid;           // 0..95 global warps
    for (int row = gw; row < 3 * HH; row += 96) {
        float4 w = ((const float4*)(W_ih + (size_t)row * OO))[lane];
        float v = w.x * x.x + w.y * x.y + w.z * x.z + w.w * x.w;
        v = warp_sum(v);
        if (lane == 0) g_gi[t][row] = v + b_ih[row];
    }
}

// ---------------- one GRU step: warp per h-row (R1-proven, untouched) ----------------
__global__ void k_gru(int t, const float* __restrict__ W_hh, const float* __restrict__ b_hh) {
    const float* hprev = g_hbuf[t & 1];
    float* hnext = g_hbuf[(t + 1) & 1];
    int gwarp = (blockIdx.x * blockDim.x + threadIdx.x) >> 5;
    int lane = threadIdx.x & 31;
    if (gwarp >= HH) return;
    int w = gwarp;
    float sr = 0.0f, sz = 0.0f, sn = 0.0f;
    const float* wr = W_hh + (size_t)w * HH;
    const float* wz = W_hh + (size_t)(HH + w) * HH;
    const float* wn = W_hh + (size_t)(2 * HH + w) * HH;
    #pragma unroll
    for (int j = 0; j < HH / 32; j++) {
        int k = lane + 32 * j;
        float hv = hprev[k];
        sr += wr[k] * hv;
        sz += wz[k] * hv;
        sn += wn[k] * hv;
    }
    #pragma unroll
    for (int off = 16; off > 0; off >>= 1) {
        sr += __shfl_down_sync(0xffffffffu, sr, off);
        sz += __shfl_down_sync(0xffffffffu, sz, off);
        sn += __shfl_down_sync(0xffffffffu, sn, off);
    }
    if (lane == 0) {
        float gh_r = sr + b_hh[w];
        float gh_z = sz + b_hh[HH + w];
        float gh_n = sn + b_hh[2 * HH + w];
        float gi_r = g_gi[t][w];
        float gi_z = g_gi[t][HH + w];
        float gi_n = g_gi[t][2 * HH + w];
        float r = 1.0f / (1.0f + expf(-(gi_r + gh_r)));
        float z = 1.0f / (1.0f + expf(-(gi_z + gh_z)));
        float nn = tanhf(gi_n + r * gh_n);
        float hn = (1.0f - z) * nn + z * hprev[w];
        hnext[w] = hn;
        g_rnn[t][w] = hn;
    }
}

// ---------------- attention + prediction head (R1-proven, untouched) ----------------
__global__ void k_head(const float* __restrict__ W_att, const float* __restrict__ b_att,
                       const float* __restrict__ W_p1, const float* __restrict__ b_p1,
                       const float* __restrict__ W_p2, const float* __restrict__ b_p2,
                       float* __restrict__ out) {
    __shared__ float att[TT], ctx[HH], red[HH];
    int tid = threadIdx.x;
    if (tid < TT) {
        float lg = b_att[0];
        for (int h = 0; h < HH; h++) lg += g_rnn[tid][h] * W_att[h];
        att[tid] = lg;
    }
    __syncthreads();
    if (tid == 0) {
        float m = att[0];
        for (int t = 1; t < TT; t++) m = fmaxf(m, att[t]);
        float s = 0.0f;
        for (int t = 0; t < TT; t++) { att[t] = expf(att[t] - m); s += att[t]; }
        for (int t = 0; t < TT; t++) att[t] /= s;
    }
    __syncthreads();
    {
        float c = 0.0f;
        #pragma unroll
        for (int t = 0; t < TT; t++) c += att[t] * g_rnn[t][tid];
        ctx[tid] = c;
    }
    __syncthreads();
    if (tid < HH / 2) {
        float v = b_p1[tid];
        const float* w = W_p1 + (size_t)tid * HH;
        #pragma unroll 8
        for (int h = 0; h < HH; h++) v += w[h] * ctx[h];
        v = fmaxf(v, 0.0f);
        red[tid] = v * W_p2[tid];
    }
    __syncthreads();
    if (tid == 0) {
        float s = b_p2[0];
        for (int j = 0; j < HH / 2; j++) s += red[j];
        out[0] = s;
    }
}

extern "C" void kernel_launch(void* const* d_in, const int* in_sizes, int n_in,
                              void* d_out, int out_size) {
    const float* x_inf  = (const float*)d_in[0];
    const float* x_item = (const float*)d_in[1];
    const int*   e1s    = (const int*)d_in[2];
    const int*   e1d    = (const int*)d_in[3];
    const int*   e2s    = (const int*)d_in[4];
    const int*   e2d    = (const int*)d_in[5];
    const int*   tgt    = (const int*)d_in[6];
    const float* W1a_l  = (const float*)d_in[7];
    const float* b1a_l  = (const float*)d_in[8];
    const float* W1a_r  = (const float*)d_in[9];
    const float* W1b_l  = (const float*)d_in[10];
    const float* b1b_l  = (const float*)d_in[11];
    const float* W1b_r  = (const float*)d_in[12];
    // d_in[13..15]: W2a_* (dead code in reference — o_item unused)
    const float* W2b_l  = (const float*)d_in[16];
    const float* b2b_l  = (const float*)d_in[17];
    const float* W2b_r  = (const float*)d_in[18];
    const float* W_ih   = (const float*)d_in[19];
    const float* W_hh   = (const float*)d_in[20];
    const float* b_ih   = (const float*)d_in[21];
    const float* b_hh   = (const float*)d_in[22];
    const float* W_att  = (const float*)d_in[23];
    const float* b_att  = (const float*)d_in[24];
    const float* W_p1   = (const float*)d_in[25];
    const float* b_p1   = (const float*)d_in[26];
    const float* W_p2   = (const float*)d_in[27];
    const float* b_p2   = (const float*)d_in[28];
    float* out = (float*)d_out;

    k_init<<<2048, 256>>>();
    dim3 gscan(SCAN_BLK, TT);
    k_scan_e2<<<gscan, 256>>>(e2s, e2d, x_item, tgt);
    k_assign<<<TT, 256>>>();
    k_scan_e1<<<gscan, 256>>>(e1s, e1d, x_inf);
    k_hitem<<<dim3(64, 8, TT), 256>>>(x_item, W1a_l, b1a_l, W1a_r);
    k_oinf<<<TT, 256>>>(x_inf, W1b_l, b1b_l, W1b_r, W2b_l, b2b_l, W2b_r, tgt);
    k_gi<<<dim3(12, TT), 256>>>(W_ih, b_ih);
    for (int t = 0; t < TT; t++)
        k_gru<<<32, 256>>>(t, W_hh, b_hh);
    k_head<<<1, 256>>>(W_att, b_att, W_p1, b_p1, W_p2, b_p2, out);
}